// round 15
// baseline (speedup 1.0000x reference)
#include <cuda_runtime.h>
#include <cuda_bf16.h>
#include <math.h>
#include <stdint.h>

// ---------------- problem constants ----------------
#define N_NODES 8192
#define N_EDGES 2048
#define L_TOK   8
#define D_EMB   64
#define FD      512
#define DG      256
#define NH      4
#define HD      64
#define VOCAB   10000
#define NROWS   (N_EDGES * L_TOK)   // 16384
#define NVT     157                  // ceil(VOCAB/64)

// ---------------- fp32 scratch ----------------
__device__ float g_x  [N_NODES * FD];
__device__ float g_msg[N_EDGES * FD];
__device__ float g_agg[N_NODES * FD];
__device__ float g_h  [N_NODES * FD];
__device__ float g_zg [NROWS * DG];
__device__ float g_qkv[NROWS * 3 * DG];
__device__ float g_x1 [NROWS * DG];
__device__ float2 g_pstat[NVT * NROWS];
__device__ float g_Ms[NROWS];
__device__ float g_Is[NROWS];

// ---------------- packed split activations: row-major [row][K/2], uint2 = {hi, lo} ----
__device__ uint2 g_se  [N_EDGES * 256];   // e    K=512
__device__ uint2 g_sx  [N_NODES * 256];   // x    K=512
__device__ uint2 g_szin[NROWS * 32];      // zin  K=64
__device__ uint2 g_szg [NROWS * 128];     // zg   K=256
__device__ uint2 g_sao [NROWS * 128];     // ao   K=256
__device__ uint2 g_sx1 [NROWS * 128];     // x1   K=256
__device__ uint2 g_sffn[NROWS * 512];     // ffn  K=1024
__device__ uint2 g_sx2 [NROWS * 128];     // x2   K=256
__device__ uint2 g_sy  [NROWS * 32];      // y    K=64

// ---------------- weight planes (packed bf16x2 word, k-major [kp][N]) ----------------
#define OFF_WMSG  0
#define OFF_WNODE (OFF_WMSG  + 256*512)
#define OFF_LC1   (OFF_WNODE + 256*512)
#define OFF_QKV   (OFF_LC1   + 32*256)
#define OFF_WO    (OFF_QKV   + 128*768)
#define OFF_WF1   (OFF_WO    + 128*256)
#define OFF_WF2   (OFF_WF1   + 128*1024)
#define OFF_LC2   (OFF_WF2   + 512*256)
#define OFF_EMB   (OFF_LC2   + 128*64)
#define TOTAL_PAIRS (OFF_EMB + VOCAB*32)
__device__ uint32_t g_whi[TOTAL_PAIRS];
__device__ uint32_t g_wlo[TOTAL_PAIRS];

// ---------------- helpers ----------------
__device__ __forceinline__ void splitpair(float x0, float x1, uint32_t& hi, uint32_t& lo) {
    __nv_bfloat162 h = __floats2bfloat162_rn(x0, x1);
    float h0 = __bfloat162float(h.x), h1 = __bfloat162float(h.y);
    __nv_bfloat162 l = __floats2bfloat162_rn(x0 - h0, x1 - h1);
    hi = *reinterpret_cast<uint32_t*>(&h);
    lo = *reinterpret_cast<uint32_t*>(&l);
}

__device__ __forceinline__ void mma16(float* c,
    uint32_t a0, uint32_t a1, uint32_t a2, uint32_t a3, uint32_t b0, uint32_t b1)
{
    asm volatile(
        "mma.sync.aligned.m16n8k16.row.col.f32.bf16.bf16.f32 "
        "{%0,%1,%2,%3},{%4,%5,%6,%7},{%8,%9},{%0,%1,%2,%3};"
        : "+f"(c[0]), "+f"(c[1]), "+f"(c[2]), "+f"(c[3])
        : "r"(a0), "r"(a1), "r"(a2), "r"(a3), "r"(b0), "r"(b1));
}

__device__ __forceinline__ float gelu_f(float v) {
    float u = 0.7978845608028654f * (v + 0.044715f * v * v * v);
    float t;
    asm("tanh.approx.f32 %0, %1;" : "=f"(t) : "f"(u));
    return 0.5f * v * (1.f + t);
}

__device__ __forceinline__ void upd_stats(float& m, float& s, float x) {
    if (x > m) { s = s * __expf(m - x) + 1.f; m = x; }
    else       { s += __expf(x - m); }
}

__device__ __forceinline__ int swz(int slot, int rc, int DIM) {
    return slot * DIM + (rc ^ ((slot & 3) << 1));
}

// ---------------- small kernels ----------------
__global__ void k_lab_embed_e(const int* __restrict__ etok, const int* __restrict__ maskbits,
                              const float* __restrict__ emb, float* __restrict__ labels_out)
{
    int i = blockIdx.x * blockDim.x + threadIdx.x;
    if (i >= NROWS * 16) return;
    int slot = i >> 4, d4 = i & 15;
    int e = slot >> 3;
    int tok = etok[slot];
    bool masked = (maskbits[e] != 0) && (tok > 3);
    int mtok = masked ? 4 : tok;
    if (d4 == 0 && labels_out) labels_out[slot] = masked ? (float)tok : -100.0f;
    float4 v = ((const float4*)emb)[mtok * 16 + d4];
    int row = slot >> 3, l = slot & 7;
    int kp0 = l * 32 + d4 * 2;
    uint32_t h0, l0, h1, l1;
    splitpair(v.x, v.y, h0, l0);
    splitpair(v.z, v.w, h1, l1);
    *(uint4*)&g_se[(size_t)row * 256 + kp0] = make_uint4(h0, l0, h1, l1);
}

__global__ void k_embed_x(const int* __restrict__ toks, const float* __restrict__ emb)
{
    int i = blockIdx.x * blockDim.x + threadIdx.x;
    if (i >= N_NODES * L_TOK * 16) return;
    int slot = i >> 4, d4 = i & 15;
    float4 v = ((const float4*)emb)[toks[slot] * 16 + d4];
    ((float4*)g_x)[i] = v;
    int row = slot >> 3, l = slot & 7;
    int kp0 = l * 32 + d4 * 2;
    uint32_t h0, l0, h1, l1;
    splitpair(v.x, v.y, h0, l0);
    splitpair(v.z, v.w, h1, l1);
    *(uint4*)&g_sx[(size_t)row * 256 + kp0] = make_uint4(h0, l0, h1, l1);
}

__device__ __forceinline__ void prep_k(const float* __restrict__ W, int N, int il, int base) {
    int kp = il / N, n = il - kp * N;
    uint32_t hi, lo;
    splitpair(W[(2 * kp) * N + n], W[(2 * kp + 1) * N + n], hi, lo);
    g_whi[base + il] = hi; g_wlo[base + il] = lo;
}

__global__ void k_prep(const float* __restrict__ Wmsg, const float* __restrict__ Wnode,
                       const float* __restrict__ lc1, const float* __restrict__ Wq,
                       const float* __restrict__ Wk, const float* __restrict__ Wv,
                       const float* __restrict__ Wo, const float* __restrict__ Wf1,
                       const float* __restrict__ Wf2, const float* __restrict__ lc2,
                       const float* __restrict__ emb)
{
    int i = blockIdx.x * blockDim.x + threadIdx.x;
    if (i >= TOTAL_PAIRS) return;
    if      (i < OFF_WNODE) prep_k(Wmsg,  512,  i - OFF_WMSG,  OFF_WMSG);
    else if (i < OFF_LC1)   prep_k(Wnode, 512,  i - OFF_WNODE, OFF_WNODE);
    else if (i < OFF_QKV)   prep_k(lc1,   256,  i - OFF_LC1,   OFF_LC1);
    else if (i < OFF_WO) {
        int il = i - OFF_QKV;
        int kp = il / 768, n = il % 768;
        const float* W = (n < 256) ? Wq : (n < 512) ? Wk : Wv;
        int nc = n & 255;
        uint32_t hi, lo;
        splitpair(W[(2 * kp) * 256 + nc], W[(2 * kp + 1) * 256 + nc], hi, lo);
        g_whi[i] = hi; g_wlo[i] = lo;
    }
    else if (i < OFF_WF1)   prep_k(Wo,    256,  i - OFF_WO,    OFF_WO);
    else if (i < OFF_WF2)   prep_k(Wf1,   1024, i - OFF_WF1,   OFF_WF1);
    else if (i < OFF_LC2)   prep_k(Wf2,   256,  i - OFF_WF2,   OFF_WF2);
    else if (i < OFF_EMB)   prep_k(lc2,   64,   i - OFF_LC2,   OFF_LC2);
    else {
        int il = i - OFF_EMB;
        int kp = il / VOCAB, n = il - kp * VOCAB;
        uint32_t hi, lo;
        splitpair(emb[n * 64 + 2 * kp], emb[n * 64 + 2 * kp + 1], hi, lo);
        g_whi[i] = hi; g_wlo[i] = lo;
    }
}

__global__ void k_zero(float* __restrict__ p, int total_f4)
{
    int i = blockIdx.x * blockDim.x + threadIdx.x;
    if (i < total_f4) ((float4*)p)[i] = make_float4(0.f, 0.f, 0.f, 0.f);
}

__global__ void k_scatter(const float* __restrict__ msg, const int* __restrict__ dst,
                          float* __restrict__ agg)
{
    int t = blockIdx.x * blockDim.x + threadIdx.x;
    if (t >= N_EDGES * FD) return;
    int e = t >> 9, c = t & 511;
    atomicAdd(&agg[dst[e] * FD + c], msg[t]);
}

__global__ void k_zin(const float* __restrict__ h, const int* __restrict__ src,
                      const int* __restrict__ dst)
{
    int i = blockIdx.x * blockDim.x + threadIdx.x;
    if (i >= NROWS * 16) return;
    int r = i >> 4, d4 = i & 15;
    int e = r >> 3, l = r & 7;
    const float4* h4 = (const float4*)h;
    float4 a = h4[src[e] * 128 + l * 16 + d4];
    float4 b = h4[dst[e] * 128 + l * 16 + d4];
    float v0 = a.x + b.x, v1 = a.y + b.y, v2 = a.z + b.z, v3 = a.w + b.w;
    uint32_t h0, l0, h1, l1;
    splitpair(v0, v1, h0, l0);
    splitpair(v2, v3, h1, l1);
    *(uint4*)&g_szin[(size_t)r * 32 + d4 * 2] = make_uint4(h0, l0, h1, l1);
}

// ---------------- bf16-split tensor GEMM: A packed split rows, B weight planes ----------
template<int ACT, bool HAS_BIAS, bool HAS_ADD, bool ADD_IDX, bool WF32, bool WSPLIT>
__global__ void __launch_bounds__(256, 2)
tgemm(const uint2* __restrict__ Asp,
      const uint32_t* __restrict__ Bhi, const uint32_t* __restrict__ Blo,
      const float* __restrict__ bias, const float* __restrict__ Add,
      const int* __restrict__ addIdx, float* __restrict__ C,
      uint2* __restrict__ Csp, int M, int N, int K)
{
    constexpr int BM = 128, BN = 64;
    constexpr int WN = 16, MT = 4, NT = 2;
    constexpr int KC = 8, JP = 4;

    extern __shared__ uint32_t dynsm[];
    uint32_t* AsW[2] = { dynsm, dynsm + BM * 32 };
    uint32_t* BsW[2] = { dynsm + 2 * BM * 32, dynsm + 2 * BM * 32 + BN * 32 };

    int tid = threadIdx.x, lane = tid & 31, w = tid >> 5;
    int g = lane >> 2, tg = lane & 3;
    int wM = w >> 2, wN = w & 3;
    int m0 = blockIdx.y * BM, n0 = blockIdx.x * BN;

    float acc[MT][NT][4];
#pragma unroll
    for (int mt = 0; mt < MT; mt++)
#pragma unroll
        for (int nt = 0; nt < NT; nt++)
#pragma unroll
            for (int c = 0; c < 4; c++) acc[mt][nt][c] = 0.f;

    int arow = tid >> 1, ahalf = tid & 1;
    int bn = tid % BN, bq = tid / BN, kb = bq * KC;
    int Kh = K >> 1;

    uint2 aw[8];
    uint32_t hw[JP], lw[JP];

    auto ldA = [&](int kt) {
        const uint2* p = Asp + (size_t)(m0 + arow) * Kh + kt * 16 + ahalf * 8;
#pragma unroll
        for (int j = 0; j < 8; j += 2) *(uint4*)&aw[j] = *(const uint4*)(p + j);
    };
    auto ldB = [&](int k0) {
        int kp0 = (k0 + kb) >> 1;
#pragma unroll
        for (int jp = 0; jp < JP; jp++) {
            size_t idx = (size_t)(kp0 + jp) * N + n0 + bn;
            hw[jp] = Bhi[idx]; lw[jp] = Blo[idx];
        }
    };
    auto stA = [&](int buf) {
#pragma unroll
        for (int j = 0; j < 8; j++) {
            int p = ahalf * 8 + j, s = p >> 3, lp = p & 7, t = lp & 3;
            int off = (lp & 4) ? 2 : 0;
            *(uint2*)&AsW[buf][swz((s << 2) | t, arow, BM) * 4 + off] = aw[j];
        }
    };
    auto stB = [&](int buf) {
#pragma unroll
        for (int jp = 0; jp < JP; jp++) {
            int p = (kb >> 1) + jp, s = p >> 3, lp = p & 7, t = lp & 3;
            int off = (lp & 4) ? 2 : 0;
            *(uint2*)&BsW[buf][swz((s << 2) | t, bn, BN) * 4 + off] = make_uint2(hw[jp], lw[jp]);
        }
    };

    int KT = K / 32;
    ldA(0); ldB(0); stA(0); stB(0);
    __syncthreads();
    for (int kt = 0; kt < KT; kt++) {
        int cur = kt & 1;
        if (kt + 1 < KT) { ldA(kt + 1); ldB((kt + 1) * 32); }
        const uint4* A4 = (const uint4*)AsW[cur];
        const uint4* B4 = (const uint4*)BsW[cur];
#pragma unroll
        for (int s = 0; s < 2; s++) {
            uint4 af[MT][2], bf[NT];
#pragma unroll
            for (int mt = 0; mt < MT; mt++) {
                int mr = wM * 64 + mt * 16 + g;
                af[mt][0] = A4[swz(s * 4 + tg, mr, BM)];
                af[mt][1] = A4[swz(s * 4 + tg, mr + 8, BM)];
            }
#pragma unroll
            for (int nt = 0; nt < NT; nt++)
                bf[nt] = B4[swz(s * 4 + tg, wN * WN + nt * 8 + g, BN)];
#pragma unroll
            for (int mt = 0; mt < MT; mt++)
#pragma unroll
                for (int nt = 0; nt < NT; nt++) {
                    mma16(acc[mt][nt], af[mt][0].x, af[mt][1].x, af[mt][0].z, af[mt][1].z,
                          bf[nt].x, bf[nt].z);
                    mma16(acc[mt][nt], af[mt][0].x, af[mt][1].x, af[mt][0].z, af[mt][1].z,
                          bf[nt].y, bf[nt].w);
                    mma16(acc[mt][nt], af[mt][0].y, af[mt][1].y, af[mt][0].w, af[mt][1].w,
                          bf[nt].x, bf[nt].z);
                }
        }
        if (kt + 1 < KT) { stA((kt + 1) & 1); stB((kt + 1) & 1); }
        __syncthreads();
    }

#pragma unroll
    for (int mt = 0; mt < MT; mt++) {
        int r1 = m0 + wM * 64 + mt * 16 + g;
        int r2 = r1 + 8;
        int a1 = r1, a2 = r2;
        if (HAS_ADD && ADD_IDX) { a1 = addIdx[r1]; a2 = addIdx[r2]; }
#pragma unroll
        for (int nt = 0; nt < NT; nt++) {
            int cb = n0 + wN * WN + nt * 8 + 2 * tg;
            float e0 = acc[mt][nt][0], e1 = acc[mt][nt][1];
            float e2 = acc[mt][nt][2], e3 = acc[mt][nt][3];
            if (HAS_BIAS) { float b0 = bias[cb], b1 = bias[cb + 1]; e0 += b0; e1 += b1; e2 += b0; e3 += b1; }
            if (HAS_ADD) {
                e0 += Add[(size_t)a1 * N + cb]; e1 += Add[(size_t)a1 * N + cb + 1];
                e2 += Add[(size_t)a2 * N + cb]; e3 += Add[(size_t)a2 * N + cb + 1];
            }
            if (ACT == 1) { e0 = fmaxf(e0, 0.f); e1 = fmaxf(e1, 0.f); e2 = fmaxf(e2, 0.f); e3 = fmaxf(e3, 0.f); }
            if (ACT == 2) { e0 = gelu_f(e0); e1 = gelu_f(e1); e2 = gelu_f(e2); e3 = gelu_f(e3); }
            if (WF32) {
                *(float2*)(C + (size_t)r1 * N + cb) = make_float2(e0, e1);
                *(float2*)(C + (size_t)r2 * N + cb) = make_float2(e2, e3);
            }
            if (WSPLIT) {
                int Nh = N >> 1;
                uint32_t hi, lo;
                splitpair(e0, e1, hi, lo);
                Csp[(size_t)r1 * Nh + (cb >> 1)] = make_uint2(hi, lo);
                splitpair(e2, e3, hi, lo);
                Csp[(size_t)r2 * Nh + (cb >> 1)] = make_uint2(hi, lo);
            }
        }
    }
}

// ---------------- lm_head GEMM (1-term bf16), two-pass: STATS then WRITE ----------------
// WRITE=false: compute logits in regs, accumulate per-tile (max,sum) partials only.
// WRITE=true:  recompute identical logits, apply exp(x-M)*I, write probs directly.
template<bool WRITE>
__global__ void __launch_bounds__(256, 2)
lmg(const uint2* __restrict__ Ysp,
    const uint32_t* __restrict__ Bhi,
    float* __restrict__ probs, float2* __restrict__ pstat)
{
    constexpr int BM = 128, BN = 64;
    constexpr int WN = 16, MT = 4, NT = 2;
    constexpr int KC = 8, JP = 4;
    const int N = VOCAB;

    extern __shared__ uint32_t dynsm[];
    uint32_t* AsW[2] = { dynsm, dynsm + BM * 32 };
    uint32_t* BsW[2] = { dynsm + 2 * BM * 32, dynsm + 2 * BM * 32 + BN * 32 };
    __shared__ float2 red[4][BM];

    int tid = threadIdx.x, lane = tid & 31, w = tid >> 5;
    int g = lane >> 2, tg = lane & 3;
    int wM = w >> 2, wN = w & 3;
    int m0 = blockIdx.y * BM, n0 = blockIdx.x * BN;

    float acc[MT][NT][4];
#pragma unroll
    for (int mt = 0; mt < MT; mt++)
#pragma unroll
        for (int nt = 0; nt < NT; nt++)
#pragma unroll
            for (int c = 0; c < 4; c++) acc[mt][nt][c] = 0.f;

    int arow = tid >> 1, ahalf = tid & 1;
    int bn = tid % BN, bq = tid / BN, kb = bq * KC;
    int bcol = n0 + bn;

    uint2 aw[8];
    uint32_t hw[JP];

    auto ldA = [&](int kt) {
        const uint2* p = Ysp + (size_t)(m0 + arow) * 32 + kt * 16 + ahalf * 8;
#pragma unroll
        for (int j = 0; j < 8; j += 2) *(uint4*)&aw[j] = *(const uint4*)(p + j);
    };
    auto ldB = [&](int k0) {
        int kp0 = (k0 + kb) >> 1;
        if (bcol < N) {
#pragma unroll
            for (int jp = 0; jp < JP; jp++)
                hw[jp] = Bhi[(size_t)(kp0 + jp) * N + bcol];
        } else {
#pragma unroll
            for (int jp = 0; jp < JP; jp++) hw[jp] = 0;
        }
    };
    auto stA = [&](int buf) {
#pragma unroll
        for (int j = 0; j < 8; j++) {
            int p = ahalf * 8 + j, s = p >> 3, lp = p & 7, t = lp & 3;
            int off = (lp & 4) ? 2 : 0;
            *(uint2*)&AsW[buf][swz((s << 2) | t, arow, BM) * 4 + off] = aw[j];
        }
    };
    auto stB = [&](int buf) {
#pragma unroll
        for (int jp = 0; jp < JP; jp++) {
            int p = (kb >> 1) + jp, s = p >> 3, lp = p & 7, t = lp & 3;
            int off = (lp & 4) ? 2 : 0;
            BsW[buf][swz((s << 2) | t, bn, BN) * 4 + off] = hw[jp];
        }
    };

    ldA(0); ldB(0); stA(0); stB(0);
    __syncthreads();
#pragma unroll
    for (int kt = 0; kt < 2; kt++) {
        int cur = kt & 1;
        if (kt == 0) { ldA(1); ldB(32); }
        const uint4* A4 = (const uint4*)AsW[cur];
        const uint4* B4 = (const uint4*)BsW[cur];
#pragma unroll
        for (int s = 0; s < 2; s++) {
            uint4 af[MT][2], bf[NT];
#pragma unroll
            for (int mt = 0; mt < MT; mt++) {
                int mr = wM * 64 + mt * 16 + g;
                af[mt][0] = A4[swz(s * 4 + tg, mr, BM)];
                af[mt][1] = A4[swz(s * 4 + tg, mr + 8, BM)];
            }
#pragma unroll
            for (int nt = 0; nt < NT; nt++)
                bf[nt] = B4[swz(s * 4 + tg, wN * WN + nt * 8 + g, BN)];
#pragma unroll
            for (int mt = 0; mt < MT; mt++)
#pragma unroll
                for (int nt = 0; nt < NT; nt++)
                    mma16(acc[mt][nt], af[mt][0].x, af[mt][1].x, af[mt][0].z, af[mt][1].z,
                          bf[nt].x, bf[nt].z);
        }
        if (kt == 0) { stA(1); stB(1); }
        __syncthreads();
    }

    if (WRITE) {
        // normalize + store probs
#pragma unroll
        for (int mt = 0; mt < MT; mt++) {
            int r1 = m0 + wM * 64 + mt * 16 + g, r2 = r1 + 8;
            float M0 = g_Ms[r1], I0 = g_Is[r1];
            float M1 = g_Ms[r2], I1 = g_Is[r2];
#pragma unroll
            for (int nt = 0; nt < NT; nt++) {
                int cb = n0 + wN * WN + nt * 8 + 2 * tg;
                if (cb < N) {
                    float p0 = __expf(acc[mt][nt][0] - M0) * I0;
                    float p1 = __expf(acc[mt][nt][1] - M0) * I0;
                    float p2 = __expf(acc[mt][nt][2] - M1) * I1;
                    float p3 = __expf(acc[mt][nt][3] - M1) * I1;
                    *(float2*)(probs + (size_t)r1 * N + cb) = make_float2(p0, p1);
                    *(float2*)(probs + (size_t)r2 * N + cb) = make_float2(p2, p3);
                }
            }
        }
    } else {
        // stats only
        float mreg[8], sreg[8];
#pragma unroll
        for (int i = 0; i < 8; i++) { mreg[i] = -1e30f; sreg[i] = 0.f; }
#pragma unroll
        for (int mt = 0; mt < MT; mt++) {
#pragma unroll
            for (int nt = 0; nt < NT; nt++) {
                int cb = n0 + wN * WN + nt * 8 + 2 * tg;
                if (cb < N) {
                    upd_stats(mreg[mt * 2], sreg[mt * 2], acc[mt][nt][0]);
                    upd_stats(mreg[mt * 2], sreg[mt * 2], acc[mt][nt][1]);
                    upd_stats(mreg[mt * 2 + 1], sreg[mt * 2 + 1], acc[mt][nt][2]);
                    upd_stats(mreg[mt * 2 + 1], sreg[mt * 2 + 1], acc[mt][nt][3]);
                }
            }
        }
#pragma unroll
        for (int i = 0; i < 8; i++) {
#pragma unroll
            for (int d = 1; d < 4; d <<= 1) {
                float om = __shfl_xor_sync(0xffffffffu, mreg[i], d);
                float os = __shfl_xor_sync(0xffffffffu, sreg[i], d);
                float M2 = fmaxf(mreg[i], om);
                sreg[i] = sreg[i] * __expf(mreg[i] - M2) + os * __expf(om - M2);
                mreg[i] = M2;
            }
        }
        if (tg == 0) {
#pragma unroll
            for (int mt = 0; mt < MT; mt++)
#pragma unroll
                for (int h = 0; h < 2; h++)
                    red[wN][wM * 64 + mt * 16 + h * 8 + g] =
                        make_float2(mreg[mt * 2 + h], sreg[mt * 2 + h]);
        }
        __syncthreads();
        if (tid < BM) {
            float M2 = -1e30f, S = 0.f;
#pragma unroll
            for (int j = 0; j < 4; j++) {
                float2 r = red[j][tid];
                float nM = fmaxf(M2, r.x);
                S = S * __expf(M2 - nM) + r.y * __expf(r.x - nM);
                M2 = nM;
            }
            pstat[(size_t)blockIdx.x * NROWS + m0 + tid] = make_float2(M2, S);
        }
    }
}

__global__ void k_red()
{
    int r = blockIdx.x * 256 + threadIdx.x;
    if (r >= NROWS) return;
    float M = -1e30f, S = 0.f;
    for (int t = 0; t < NVT; t++) {
        float2 p = g_pstat[(size_t)t * NROWS + r];
        float nM = fmaxf(M, p.x);
        S = S * __expf(M - nM) + p.y * __expf(p.x - nM);
        M = nM;
    }
    g_Ms[r] = M;
    g_Is[r] = 1.f / S;
}

// ---------------- attention (reads fused qkv [row][768], writes packed split ao) --------
__global__ void __launch_bounds__(256)
k_attn(const float* __restrict__ QKV)
{
    int e = blockIdx.x;
    int tid = threadIdx.x;
    __shared__ float qs[8][DG], ks[8][DG], vs[8][DG];
    __shared__ float att[NH][8][8];

    for (int i = tid; i < 8 * DG; i += 256) {
        int s = i >> 8, c = i & 255;
        size_t base = (size_t)(e * 8 + s) * 768 + c;
        qs[s][c] = QKV[base]; ks[s][c] = QKV[base + 256]; vs[s][c] = QKV[base + 512];
    }
    __syncthreads();
    {
        int h = tid >> 6, rem = tid & 63, qi = rem >> 3, ki = rem & 7;
        float acc = 0.f;
#pragma unroll
        for (int d = 0; d < HD; d++) acc = fmaf(qs[qi][h * HD + d], ks[ki][h * HD + d], acc);
        att[h][qi][ki] = acc * 0.125f;
    }
    __syncthreads();
    if (tid < 32) {
        int h = tid >> 3, qi = tid & 7;
        float m = -1e30f;
#pragma unroll
        for (int ki = 0; ki < 8; ki++) m = fmaxf(m, att[h][qi][ki]);
        float s = 0.f, ex[8];
#pragma unroll
        for (int ki = 0; ki < 8; ki++) { ex[ki] = __expf(att[h][qi][ki] - m); s += ex[ki]; }
        float inv = 1.f / s;
#pragma unroll
        for (int ki = 0; ki < 8; ki++) att[h][qi][ki] = ex[ki] * inv;
    }
    __syncthreads();
    {
        int c = tid, h = c >> 6;
#pragma unroll
        for (int s = 0; s < 8; s++) {
            float acc = 0.f;
#pragma unroll
            for (int ki = 0; ki < 8; ki++) acc = fmaf(att[h][s][ki], vs[ki][c], acc);
            float vn = __shfl_down_sync(0xffffffffu, acc, 1);
            if ((c & 1) == 0) {
                uint32_t hi, lo;
                splitpair(acc, vn, hi, lo);
                g_sao[(size_t)(e * 8 + s) * 128 + (c >> 1)] = make_uint2(hi, lo);
            }
        }
    }
}

// ---------------- host launcher ----------------
extern "C" void kernel_launch(void* const* d_in, const int* in_sizes, int n_in,
                              void* d_out, int out_size)
{
    const int*   node_tokens = (const int*)d_in[0];
    const int*   edge_tokens = (const int*)d_in[1];
    const int*   edge_index  = (const int*)d_in[2];
    const int*   mask_rows   = (const int*)d_in[3];
    const float* emb   = (const float*)d_in[4];
    const float* W_msg = (const float*)d_in[5];
    const float* W_node= (const float*)d_in[6];
    const float* lc1_w = (const float*)d_in[7];
    const float* lc1_b = (const float*)d_in[8];
    const float* lc2_w = (const float*)d_in[9];
    const float* lc2_b = (const float*)d_in[10];
    const float* Wq  = (const float*)d_in[11];
    const float* Wk  = (const float*)d_in[12];
    const float* Wv  = (const float*)d_in[13];
    const float* Wo  = (const float*)d_in[14];
    const float* Wf1 = (const float*)d_in[15];
    const float* Wf2 = (const float*)d_in[16];
    const int* src = edge_index;
    const int* dst = edge_index + N_EDGES;

    float *p_x, *p_msg, *p_agg, *p_h, *p_zg, *p_qkv, *p_x1;
    float2* p_pstat;
    uint32_t *whi, *wlo;
    uint2 *sse, *ssx, *sszin, *sszg, *ssao, *ssx1, *ssffn, *ssx2, *ssy;
    cudaGetSymbolAddress((void**)&p_x,   g_x);
    cudaGetSymbolAddress((void**)&p_msg, g_msg);
    cudaGetSymbolAddress((void**)&p_agg, g_agg);
    cudaGetSymbolAddress((void**)&p_h,   g_h);
    cudaGetSymbolAddress((void**)&p_zg,  g_zg);
    cudaGetSymbolAddress((void**)&p_qkv, g_qkv);
    cudaGetSymbolAddress((void**)&p_x1,  g_x1);
    cudaGetSymbolAddress((void**)&p_pstat, g_pstat);
    cudaGetSymbolAddress((void**)&whi,   g_whi);
    cudaGetSymbolAddress((void**)&wlo,   g_wlo);
    cudaGetSymbolAddress((void**)&sse,   g_se);
    cudaGetSymbolAddress((void**)&ssx,   g_sx);
    cudaGetSymbolAddress((void**)&sszin, g_szin);
    cudaGetSymbolAddress((void**)&sszg,  g_szg);
    cudaGetSymbolAddress((void**)&ssao,  g_sao);
    cudaGetSymbolAddress((void**)&ssx1,  g_sx1);
    cudaGetSymbolAddress((void**)&ssffn, g_sffn);
    cudaGetSymbolAddress((void**)&ssx2,  g_sx2);
    cudaGetSymbolAddress((void**)&ssy,   g_sy);

    const int SMG = (2 * 128 * 32 + 2 * 64 * 32) * 4;   // 48KB
    cudaFuncSetAttribute(tgemm<1, false, true, true, true, false>,   cudaFuncAttributeMaxDynamicSharedMemorySize, SMG);
    cudaFuncSetAttribute(tgemm<1, false, true, false, true, false>,  cudaFuncAttributeMaxDynamicSharedMemorySize, SMG);
    cudaFuncSetAttribute(tgemm<0, true, false, false, true, true>,   cudaFuncAttributeMaxDynamicSharedMemorySize, SMG);
    cudaFuncSetAttribute(tgemm<0, false, false, false, true, false>, cudaFuncAttributeMaxDynamicSharedMemorySize, SMG);
    cudaFuncSetAttribute(tgemm<0, false, true, false, true, true>,   cudaFuncAttributeMaxDynamicSharedMemorySize, SMG);
    cudaFuncSetAttribute(tgemm<2, false, false, false, false, true>, cudaFuncAttributeMaxDynamicSharedMemorySize, SMG);
    cudaFuncSetAttribute(tgemm<0, false, true, false, false, true>,  cudaFuncAttributeMaxDynamicSharedMemorySize, SMG);
    cudaFuncSetAttribute(tgemm<0, true, false, false, false, true>,  cudaFuncAttributeMaxDynamicSharedMemorySize, SMG);
    cudaFuncSetAttribute(lmg<false>, cudaFuncAttributeMaxDynamicSharedMemorySize, SMG);
    cudaFuncSetAttribute(lmg<true>,  cudaFuncAttributeMaxDynamicSharedMemorySize, SMG);

    // output layout: probs-only, or labels(16384) ++ probs
    float* out = (float*)d_out;
    const long long PROBS_N = (long long)NROWS * VOCAB;
    float* labels_out = nullptr;
    float* probs = out;
    if ((long long)out_size >= PROBS_N + NROWS) { labels_out = out; probs = out + NROWS; }

    // 1) embeds + weight presplit
    k_lab_embed_e<<<(NROWS * 16) / 256, 256>>>(edge_tokens, mask_rows, emb, labels_out);
    k_embed_x<<<(N_NODES * L_TOK * 16) / 256, 256>>>(node_tokens, emb);
    k_prep<<<(TOTAL_PAIRS + 255) / 256, 256>>>(W_msg, W_node, lc1_w, Wq, Wk, Wv, Wo, Wf1, Wf2, lc2_w, emb);

    // 2) GNN
    tgemm<1, false, true, true, true, false><<<dim3(FD / 64, N_EDGES / 128), 256, SMG>>>(
        sse, whi + OFF_WMSG, wlo + OFF_WMSG, nullptr, p_x, src, p_msg, nullptr, N_EDGES, FD, FD);
    k_zero<<<(N_NODES * FD / 4) / 256, 256>>>(p_agg, N_NODES * FD / 4);
    k_scatter<<<(N_EDGES * FD) / 256, 256>>>(p_msg, dst, p_agg);
    tgemm<1, false, true, false, true, false><<<dim3(FD / 64, N_NODES / 128), 256, SMG>>>(
        ssx, whi + OFF_WNODE, wlo + OFF_WNODE, nullptr, p_agg, nullptr, p_h, nullptr, N_NODES, FD, FD);

    // 3) eh gather + lc1
    k_zin<<<(NROWS * 16) / 256, 256>>>(p_h, src, dst);
    tgemm<0, true, false, false, true, true><<<dim3(DG / 64, NROWS / 128), 256, SMG>>>(
        sszin, whi + OFF_LC1, wlo + OFF_LC1, lc1_b, nullptr, nullptr, p_zg, sszg, NROWS, DG, D_EMB);

    // 4) transformer
    tgemm<0, false, false, false, true, false><<<dim3(768 / 64, NROWS / 128), 256, SMG>>>(
        sszg, whi + OFF_QKV, wlo + OFF_QKV, nullptr, nullptr, nullptr, p_qkv, nullptr, NROWS, 768, DG);
    k_attn<<<N_EDGES, 256>>>(p_qkv);
    tgemm<0, false, true, false, true, true><<<dim3(DG / 64, NROWS / 128), 256, SMG>>>(
        ssao, whi + OFF_WO, wlo + OFF_WO, nullptr, p_zg, nullptr, p_x1, ssx1, NROWS, DG, DG);
    tgemm<2, false, false, false, false, true><<<dim3(4 * DG / 64, NROWS / 128), 256, SMG>>>(
        ssx1, whi + OFF_WF1, wlo + OFF_WF1, nullptr, nullptr, nullptr, nullptr, ssffn, NROWS, 4 * DG, DG);
    tgemm<0, false, true, false, false, true><<<dim3(DG / 64, NROWS / 128), 256, SMG>>>(
        ssffn, whi + OFF_WF2, wlo + OFF_WF2, nullptr, p_x1, nullptr, nullptr, ssx2, NROWS, DG, 4 * DG);

    // 5) lc2 -> y (split only)
    tgemm<0, true, false, false, false, true><<<dim3(1, NROWS / 128), 256, SMG>>>(
        ssx2, whi + OFF_LC2, wlo + OFF_LC2, lc2_b, nullptr, nullptr, nullptr, ssy, NROWS, D_EMB, DG);

    // 6) lm head two-pass: stats (no logit store) -> reduce -> recompute+normalize+write
    lmg<false><<<dim3(NVT, NROWS / 128), 256, SMG>>>(ssy, whi + OFF_EMB, nullptr, p_pstat);
    k_red<<<NROWS / 256, 256>>>();
    lmg<true><<<dim3(NVT, NROWS / 128), 256, SMG>>>(ssy, whi + OFF_EMB, probs, p_pstat);
}

// round 16
// speedup vs baseline: 1.1407x; 1.1407x over previous
#include <cuda_runtime.h>
#include <cuda_bf16.h>
#include <math.h>
#include <stdint.h>

// ---------------- problem constants ----------------
#define N_NODES 8192
#define N_EDGES 2048
#define L_TOK   8
#define D_EMB   64
#define FD      512
#define DG      256
#define NH      4
#define HD      64
#define VOCAB   10000
#define NROWS   (N_EDGES * L_TOK)   // 16384
#define NVT     157                  // ceil(VOCAB/64)
#define VH      (VOCAB / 2)          // 5000 packed bf16 pairs per row

// ---------------- fp32 scratch ----------------
__device__ float g_x  [N_NODES * FD];
__device__ float g_msg[N_EDGES * FD];
__device__ float g_agg[N_NODES * FD];
__device__ float g_h  [N_NODES * FD];
__device__ float g_zg [NROWS * DG];
__device__ float g_qkv[NROWS * 3 * DG];
__device__ float g_x1 [NROWS * DG];
__device__ float2 g_pstat[NVT * NROWS];
__device__ float g_Ms[NROWS];
__device__ float g_Is[NROWS];
__device__ uint32_t g_lbf[(size_t)NROWS * VH];   // packed bf16 logits (327 MB)

// ---------------- packed split activations: row-major [row][K/2], uint2 = {hi, lo} ----
__device__ uint2 g_se  [N_EDGES * 256];
__device__ uint2 g_sx  [N_NODES * 256];
__device__ uint2 g_szin[NROWS * 32];
__device__ uint2 g_szg [NROWS * 128];
__device__ uint2 g_sao [NROWS * 128];
__device__ uint2 g_sx1 [NROWS * 128];
__device__ uint2 g_sffn[NROWS * 512];
__device__ uint2 g_sx2 [NROWS * 128];
__device__ uint2 g_sy  [NROWS * 32];

// ---------------- weight planes (packed bf16x2 word, k-major [kp][N]) ----------------
#define OFF_WMSG  0
#define OFF_WNODE (OFF_WMSG  + 256*512)
#define OFF_LC1   (OFF_WNODE + 256*512)
#define OFF_QKV   (OFF_LC1   + 32*256)
#define OFF_WO    (OFF_QKV   + 128*768)
#define OFF_WF1   (OFF_WO    + 128*256)
#define OFF_WF2   (OFF_WF1   + 128*1024)
#define OFF_LC2   (OFF_WF2   + 512*256)
#define OFF_EMB   (OFF_LC2   + 128*64)
#define TOTAL_PAIRS (OFF_EMB + VOCAB*32)
__device__ uint32_t g_whi[TOTAL_PAIRS];
__device__ uint32_t g_wlo[TOTAL_PAIRS];

// ---------------- helpers ----------------
__device__ __forceinline__ void splitpair(float x0, float x1, uint32_t& hi, uint32_t& lo) {
    __nv_bfloat162 h = __floats2bfloat162_rn(x0, x1);
    float h0 = __bfloat162float(h.x), h1 = __bfloat162float(h.y);
    __nv_bfloat162 l = __floats2bfloat162_rn(x0 - h0, x1 - h1);
    hi = *reinterpret_cast<uint32_t*>(&h);
    lo = *reinterpret_cast<uint32_t*>(&l);
}

__device__ __forceinline__ uint32_t packbf(float x0, float x1) {
    __nv_bfloat162 h = __floats2bfloat162_rn(x0, x1);
    return *reinterpret_cast<uint32_t*>(&h);
}

__device__ __forceinline__ void mma16(float* c,
    uint32_t a0, uint32_t a1, uint32_t a2, uint32_t a3, uint32_t b0, uint32_t b1)
{
    asm volatile(
        "mma.sync.aligned.m16n8k16.row.col.f32.bf16.bf16.f32 "
        "{%0,%1,%2,%3},{%4,%5,%6,%7},{%8,%9},{%0,%1,%2,%3};"
        : "+f"(c[0]), "+f"(c[1]), "+f"(c[2]), "+f"(c[3])
        : "r"(a0), "r"(a1), "r"(a2), "r"(a3), "r"(b0), "r"(b1));
}

__device__ __forceinline__ float gelu_f(float v) {
    float u = 0.7978845608028654f * (v + 0.044715f * v * v * v);
    float t;
    asm("tanh.approx.f32 %0, %1;" : "=f"(t) : "f"(u));
    return 0.5f * v * (1.f + t);
}

__device__ __forceinline__ void upd_stats(float& m, float& s, float x) {
    if (x > m) { s = s * __expf(m - x) + 1.f; m = x; }
    else       { s += __expf(x - m); }
}

__device__ __forceinline__ int swz(int slot, int rc, int DIM) {
    return slot * DIM + (rc ^ ((slot & 3) << 1));
}

// ---------------- small kernels ----------------
__global__ void k_lab_embed_e(const int* __restrict__ etok, const int* __restrict__ maskbits,
                              const float* __restrict__ emb, float* __restrict__ labels_out)
{
    int i = blockIdx.x * blockDim.x + threadIdx.x;
    if (i >= NROWS * 16) return;
    int slot = i >> 4, d4 = i & 15;
    int e = slot >> 3;
    int tok = etok[slot];
    bool masked = (maskbits[e] != 0) && (tok > 3);
    int mtok = masked ? 4 : tok;
    if (d4 == 0 && labels_out) labels_out[slot] = masked ? (float)tok : -100.0f;
    float4 v = ((const float4*)emb)[mtok * 16 + d4];
    int row = slot >> 3, l = slot & 7;
    int kp0 = l * 32 + d4 * 2;
    uint32_t h0, l0, h1, l1;
    splitpair(v.x, v.y, h0, l0);
    splitpair(v.z, v.w, h1, l1);
    *(uint4*)&g_se[(size_t)row * 256 + kp0] = make_uint4(h0, l0, h1, l1);
}

__global__ void k_embed_x(const int* __restrict__ toks, const float* __restrict__ emb)
{
    int i = blockIdx.x * blockDim.x + threadIdx.x;
    if (i >= N_NODES * L_TOK * 16) return;
    int slot = i >> 4, d4 = i & 15;
    float4 v = ((const float4*)emb)[toks[slot] * 16 + d4];
    ((float4*)g_x)[i] = v;
    int row = slot >> 3, l = slot & 7;
    int kp0 = l * 32 + d4 * 2;
    uint32_t h0, l0, h1, l1;
    splitpair(v.x, v.y, h0, l0);
    splitpair(v.z, v.w, h1, l1);
    *(uint4*)&g_sx[(size_t)row * 256 + kp0] = make_uint4(h0, l0, h1, l1);
}

__device__ __forceinline__ void prep_k(const float* __restrict__ W, int N, int il, int base) {
    int kp = il / N, n = il - kp * N;
    uint32_t hi, lo;
    splitpair(W[(2 * kp) * N + n], W[(2 * kp + 1) * N + n], hi, lo);
    g_whi[base + il] = hi; g_wlo[base + il] = lo;
}

__global__ void k_prep(const float* __restrict__ Wmsg, const float* __restrict__ Wnode,
                       const float* __restrict__ lc1, const float* __restrict__ Wq,
                       const float* __restrict__ Wk, const float* __restrict__ Wv,
                       const float* __restrict__ Wo, const float* __restrict__ Wf1,
                       const float* __restrict__ Wf2, const float* __restrict__ lc2,
                       const float* __restrict__ emb)
{
    int i = blockIdx.x * blockDim.x + threadIdx.x;
    if (i >= TOTAL_PAIRS) return;
    if      (i < OFF_WNODE) prep_k(Wmsg,  512,  i - OFF_WMSG,  OFF_WMSG);
    else if (i < OFF_LC1)   prep_k(Wnode, 512,  i - OFF_WNODE, OFF_WNODE);
    else if (i < OFF_QKV)   prep_k(lc1,   256,  i - OFF_LC1,   OFF_LC1);
    else if (i < OFF_WO) {
        int il = i - OFF_QKV;
        int kp = il / 768, n = il % 768;
        const float* W = (n < 256) ? Wq : (n < 512) ? Wk : Wv;
        int nc = n & 255;
        uint32_t hi, lo;
        splitpair(W[(2 * kp) * 256 + nc], W[(2 * kp + 1) * 256 + nc], hi, lo);
        g_whi[i] = hi; g_wlo[i] = lo;
    }
    else if (i < OFF_WF1)   prep_k(Wo,    256,  i - OFF_WO,    OFF_WO);
    else if (i < OFF_WF2)   prep_k(Wf1,   1024, i - OFF_WF1,   OFF_WF1);
    else if (i < OFF_LC2)   prep_k(Wf2,   256,  i - OFF_WF2,   OFF_WF2);
    else if (i < OFF_EMB)   prep_k(lc2,   64,   i - OFF_LC2,   OFF_LC2);
    else {
        int il = i - OFF_EMB;
        int kp = il / VOCAB, n = il - kp * VOCAB;
        uint32_t hi, lo;
        splitpair(emb[n * 64 + 2 * kp], emb[n * 64 + 2 * kp + 1], hi, lo);
        g_whi[i] = hi; g_wlo[i] = lo;
    }
}

__global__ void k_zero(float* __restrict__ p, int total_f4)
{
    int i = blockIdx.x * blockDim.x + threadIdx.x;
    if (i < total_f4) ((float4*)p)[i] = make_float4(0.f, 0.f, 0.f, 0.f);
}

__global__ void k_scatter(const float* __restrict__ msg, const int* __restrict__ dst,
                          float* __restrict__ agg)
{
    int t = blockIdx.x * blockDim.x + threadIdx.x;
    if (t >= N_EDGES * FD) return;
    int e = t >> 9, c = t & 511;
    atomicAdd(&agg[dst[e] * FD + c], msg[t]);
}

__global__ void k_zin(const float* __restrict__ h, const int* __restrict__ src,
                      const int* __restrict__ dst)
{
    int i = blockIdx.x * blockDim.x + threadIdx.x;
    if (i >= NROWS * 16) return;
    int r = i >> 4, d4 = i & 15;
    int e = r >> 3, l = r & 7;
    const float4* h4 = (const float4*)h;
    float4 a = h4[src[e] * 128 + l * 16 + d4];
    float4 b = h4[dst[e] * 128 + l * 16 + d4];
    float v0 = a.x + b.x, v1 = a.y + b.y, v2 = a.z + b.z, v3 = a.w + b.w;
    uint32_t h0, l0, h1, l1;
    splitpair(v0, v1, h0, l0);
    splitpair(v2, v3, h1, l1);
    *(uint4*)&g_szin[(size_t)r * 32 + d4 * 2] = make_uint4(h0, l0, h1, l1);
}

// ---------------- bf16-split tensor GEMM: A packed split rows, B weight planes ----------
template<int ACT, bool HAS_BIAS, bool HAS_ADD, bool ADD_IDX, bool WF32, bool WSPLIT>
__global__ void __launch_bounds__(256, 2)
tgemm(const uint2* __restrict__ Asp,
      const uint32_t* __restrict__ Bhi, const uint32_t* __restrict__ Blo,
      const float* __restrict__ bias, const float* __restrict__ Add,
      const int* __restrict__ addIdx, float* __restrict__ C,
      uint2* __restrict__ Csp, int M, int N, int K)
{
    constexpr int BM = 128, BN = 64;
    constexpr int WN = 16, MT = 4, NT = 2;
    constexpr int KC = 8, JP = 4;

    extern __shared__ uint32_t dynsm[];
    uint32_t* AsW[2] = { dynsm, dynsm + BM * 32 };
    uint32_t* BsW[2] = { dynsm + 2 * BM * 32, dynsm + 2 * BM * 32 + BN * 32 };

    int tid = threadIdx.x, lane = tid & 31, w = tid >> 5;
    int g = lane >> 2, tg = lane & 3;
    int wM = w >> 2, wN = w & 3;
    int m0 = blockIdx.y * BM, n0 = blockIdx.x * BN;

    float acc[MT][NT][4];
#pragma unroll
    for (int mt = 0; mt < MT; mt++)
#pragma unroll
        for (int nt = 0; nt < NT; nt++)
#pragma unroll
            for (int c = 0; c < 4; c++) acc[mt][nt][c] = 0.f;

    int arow = tid >> 1, ahalf = tid & 1;
    int bn = tid % BN, bq = tid / BN, kb = bq * KC;
    int Kh = K >> 1;

    uint2 aw[8];
    uint32_t hw[JP], lw[JP];

    auto ldA = [&](int kt) {
        const uint2* p = Asp + (size_t)(m0 + arow) * Kh + kt * 16 + ahalf * 8;
#pragma unroll
        for (int j = 0; j < 8; j += 2) *(uint4*)&aw[j] = *(const uint4*)(p + j);
    };
    auto ldB = [&](int k0) {
        int kp0 = (k0 + kb) >> 1;
#pragma unroll
        for (int jp = 0; jp < JP; jp++) {
            size_t idx = (size_t)(kp0 + jp) * N + n0 + bn;
            hw[jp] = Bhi[idx]; lw[jp] = Blo[idx];
        }
    };
    auto stA = [&](int buf) {
#pragma unroll
        for (int j = 0; j < 8; j++) {
            int p = ahalf * 8 + j, s = p >> 3, lp = p & 7, t = lp & 3;
            int off = (lp & 4) ? 2 : 0;
            *(uint2*)&AsW[buf][swz((s << 2) | t, arow, BM) * 4 + off] = aw[j];
        }
    };
    auto stB = [&](int buf) {
#pragma unroll
        for (int jp = 0; jp < JP; jp++) {
            int p = (kb >> 1) + jp, s = p >> 3, lp = p & 7, t = lp & 3;
            int off = (lp & 4) ? 2 : 0;
            *(uint2*)&BsW[buf][swz((s << 2) | t, bn, BN) * 4 + off] = make_uint2(hw[jp], lw[jp]);
        }
    };

    int KT = K / 32;
    ldA(0); ldB(0); stA(0); stB(0);
    __syncthreads();
    for (int kt = 0; kt < KT; kt++) {
        int cur = kt & 1;
        if (kt + 1 < KT) { ldA(kt + 1); ldB((kt + 1) * 32); }
        const uint4* A4 = (const uint4*)AsW[cur];
        const uint4* B4 = (const uint4*)BsW[cur];
#pragma unroll
        for (int s = 0; s < 2; s++) {
            uint4 af[MT][2], bf[NT];
#pragma unroll
            for (int mt = 0; mt < MT; mt++) {
                int mr = wM * 64 + mt * 16 + g;
                af[mt][0] = A4[swz(s * 4 + tg, mr, BM)];
                af[mt][1] = A4[swz(s * 4 + tg, mr + 8, BM)];
            }
#pragma unroll
            for (int nt = 0; nt < NT; nt++)
                bf[nt] = B4[swz(s * 4 + tg, wN * WN + nt * 8 + g, BN)];
#pragma unroll
            for (int mt = 0; mt < MT; mt++)
#pragma unroll
                for (int nt = 0; nt < NT; nt++) {
                    mma16(acc[mt][nt], af[mt][0].x, af[mt][1].x, af[mt][0].z, af[mt][1].z,
                          bf[nt].x, bf[nt].z);
                    mma16(acc[mt][nt], af[mt][0].x, af[mt][1].x, af[mt][0].z, af[mt][1].z,
                          bf[nt].y, bf[nt].w);
                    mma16(acc[mt][nt], af[mt][0].y, af[mt][1].y, af[mt][0].w, af[mt][1].w,
                          bf[nt].x, bf[nt].z);
                }
        }
        if (kt + 1 < KT) { stA((kt + 1) & 1); stB((kt + 1) & 1); }
        __syncthreads();
    }

#pragma unroll
    for (int mt = 0; mt < MT; mt++) {
        int r1 = m0 + wM * 64 + mt * 16 + g;
        int r2 = r1 + 8;
        int a1 = r1, a2 = r2;
        if (HAS_ADD && ADD_IDX) { a1 = addIdx[r1]; a2 = addIdx[r2]; }
#pragma unroll
        for (int nt = 0; nt < NT; nt++) {
            int cb = n0 + wN * WN + nt * 8 + 2 * tg;
            float e0 = acc[mt][nt][0], e1 = acc[mt][nt][1];
            float e2 = acc[mt][nt][2], e3 = acc[mt][nt][3];
            if (HAS_BIAS) { float b0 = bias[cb], b1 = bias[cb + 1]; e0 += b0; e1 += b1; e2 += b0; e3 += b1; }
            if (HAS_ADD) {
                e0 += Add[(size_t)a1 * N + cb]; e1 += Add[(size_t)a1 * N + cb + 1];
                e2 += Add[(size_t)a2 * N + cb]; e3 += Add[(size_t)a2 * N + cb + 1];
            }
            if (ACT == 1) { e0 = fmaxf(e0, 0.f); e1 = fmaxf(e1, 0.f); e2 = fmaxf(e2, 0.f); e3 = fmaxf(e3, 0.f); }
            if (ACT == 2) { e0 = gelu_f(e0); e1 = gelu_f(e1); e2 = gelu_f(e2); e3 = gelu_f(e3); }
            if (WF32) {
                *(float2*)(C + (size_t)r1 * N + cb) = make_float2(e0, e1);
                *(float2*)(C + (size_t)r2 * N + cb) = make_float2(e2, e3);
            }
            if (WSPLIT) {
                int Nh = N >> 1;
                uint32_t hi, lo;
                splitpair(e0, e1, hi, lo);
                Csp[(size_t)r1 * Nh + (cb >> 1)] = make_uint2(hi, lo);
                splitpair(e2, e3, hi, lo);
                Csp[(size_t)r2 * Nh + (cb >> 1)] = make_uint2(hi, lo);
            }
        }
    }
}

// ---------------- lm_head GEMM (1-term bf16) + bf16 logit store + partial stats ----------
__global__ void __launch_bounds__(256, 2)
lmg(const uint2* __restrict__ Ysp,
    const uint32_t* __restrict__ Bhi,
    uint32_t* __restrict__ lbf, float2* __restrict__ pstat)
{
    constexpr int BM = 128, BN = 64;
    constexpr int WN = 16, MT = 4, NT = 2;
    constexpr int KC = 8, JP = 4;
    const int N = VOCAB;

    extern __shared__ uint32_t dynsm[];
    uint32_t* AsW[2] = { dynsm, dynsm + BM * 32 };
    uint32_t* BsW[2] = { dynsm + 2 * BM * 32, dynsm + 2 * BM * 32 + BN * 32 };
    __shared__ float2 red[4][BM];

    int tid = threadIdx.x, lane = tid & 31, w = tid >> 5;
    int g = lane >> 2, tg = lane & 3;
    int wM = w >> 2, wN = w & 3;
    int m0 = blockIdx.y * BM, n0 = blockIdx.x * BN;

    float acc[MT][NT][4];
#pragma unroll
    for (int mt = 0; mt < MT; mt++)
#pragma unroll
        for (int nt = 0; nt < NT; nt++)
#pragma unroll
            for (int c = 0; c < 4; c++) acc[mt][nt][c] = 0.f;

    int arow = tid >> 1, ahalf = tid & 1;
    int bn = tid % BN, bq = tid / BN, kb = bq * KC;
    int bcol = n0 + bn;

    uint2 aw[8];
    uint32_t hw[JP];

    auto ldA = [&](int kt) {
        const uint2* p = Ysp + (size_t)(m0 + arow) * 32 + kt * 16 + ahalf * 8;
#pragma unroll
        for (int j = 0; j < 8; j += 2) *(uint4*)&aw[j] = *(const uint4*)(p + j);
    };
    auto ldB = [&](int k0) {
        int kp0 = (k0 + kb) >> 1;
        if (bcol < N) {
#pragma unroll
            for (int jp = 0; jp < JP; jp++)
                hw[jp] = Bhi[(size_t)(kp0 + jp) * N + bcol];
        } else {
#pragma unroll
            for (int jp = 0; jp < JP; jp++) hw[jp] = 0;
        }
    };
    auto stA = [&](int buf) {
#pragma unroll
        for (int j = 0; j < 8; j++) {
            int p = ahalf * 8 + j, s = p >> 3, lp = p & 7, t = lp & 3;
            int off = (lp & 4) ? 2 : 0;
            *(uint2*)&AsW[buf][swz((s << 2) | t, arow, BM) * 4 + off] = aw[j];
        }
    };
    auto stB = [&](int buf) {
#pragma unroll
        for (int jp = 0; jp < JP; jp++) {
            int p = (kb >> 1) + jp, s = p >> 3, lp = p & 7, t = lp & 3;
            int off = (lp & 4) ? 2 : 0;
            BsW[buf][swz((s << 2) | t, bn, BN) * 4 + off] = hw[jp];
        }
    };

    ldA(0); ldB(0); stA(0); stB(0);
    __syncthreads();
#pragma unroll
    for (int kt = 0; kt < 2; kt++) {
        int cur = kt & 1;
        if (kt == 0) { ldA(1); ldB(32); }
        const uint4* A4 = (const uint4*)AsW[cur];
        const uint4* B4 = (const uint4*)BsW[cur];
#pragma unroll
        for (int s = 0; s < 2; s++) {
            uint4 af[MT][2], bf[NT];
#pragma unroll
            for (int mt = 0; mt < MT; mt++) {
                int mr = wM * 64 + mt * 16 + g;
                af[mt][0] = A4[swz(s * 4 + tg, mr, BM)];
                af[mt][1] = A4[swz(s * 4 + tg, mr + 8, BM)];
            }
#pragma unroll
            for (int nt = 0; nt < NT; nt++)
                bf[nt] = B4[swz(s * 4 + tg, wN * WN + nt * 8 + g, BN)];
#pragma unroll
            for (int mt = 0; mt < MT; mt++)
#pragma unroll
                for (int nt = 0; nt < NT; nt++)
                    mma16(acc[mt][nt], af[mt][0].x, af[mt][1].x, af[mt][0].z, af[mt][1].z,
                          bf[nt].x, bf[nt].z);
        }
        if (kt == 0) { stA(1); stB(1); }
        __syncthreads();
    }

    float mreg[8], sreg[8];
#pragma unroll
    for (int i = 0; i < 8; i++) { mreg[i] = -1e30f; sreg[i] = 0.f; }

#pragma unroll
    for (int mt = 0; mt < MT; mt++) {
        int r1 = m0 + wM * 64 + mt * 16 + g, r2 = r1 + 8;
#pragma unroll
        for (int nt = 0; nt < NT; nt++) {
            int cb = n0 + wN * WN + nt * 8 + 2 * tg;
            if (cb < N) {
                float e0 = acc[mt][nt][0], e1 = acc[mt][nt][1];
                float e2 = acc[mt][nt][2], e3 = acc[mt][nt][3];
                lbf[(size_t)r1 * VH + (cb >> 1)] = packbf(e0, e1);
                lbf[(size_t)r2 * VH + (cb >> 1)] = packbf(e2, e3);
                upd_stats(mreg[mt * 2], sreg[mt * 2], e0);
                upd_stats(mreg[mt * 2], sreg[mt * 2], e1);
                upd_stats(mreg[mt * 2 + 1], sreg[mt * 2 + 1], e2);
                upd_stats(mreg[mt * 2 + 1], sreg[mt * 2 + 1], e3);
            }
        }
    }
#pragma unroll
    for (int i = 0; i < 8; i++) {
#pragma unroll
        for (int d = 1; d < 4; d <<= 1) {
            float om = __shfl_xor_sync(0xffffffffu, mreg[i], d);
            float os = __shfl_xor_sync(0xffffffffu, sreg[i], d);
            float M2 = fmaxf(mreg[i], om);
            sreg[i] = sreg[i] * __expf(mreg[i] - M2) + os * __expf(om - M2);
            mreg[i] = M2;
        }
    }
    if (tg == 0) {
#pragma unroll
        for (int mt = 0; mt < MT; mt++)
#pragma unroll
            for (int h = 0; h < 2; h++)
                red[wN][wM * 64 + mt * 16 + h * 8 + g] =
                    make_float2(mreg[mt * 2 + h], sreg[mt * 2 + h]);
    }
    __syncthreads();
    if (tid < BM) {
        float M2 = -1e30f, S = 0.f;
#pragma unroll
        for (int j = 0; j < 4; j++) {
            float2 r = red[j][tid];
            float nM = fmaxf(M2, r.x);
            S = S * __expf(M2 - nM) + r.y * __expf(r.x - nM);
            M2 = nM;
        }
        pstat[(size_t)blockIdx.x * NROWS + m0 + tid] = make_float2(M2, S);
    }
}

__global__ void k_red()
{
    int r = blockIdx.x * 256 + threadIdx.x;
    if (r >= NROWS) return;
    float M = -1e30f, S = 0.f;
    for (int t = 0; t < NVT; t++) {
        float2 p = g_pstat[(size_t)t * NROWS + r];
        float nM = fmaxf(M, p.x);
        S = S * __expf(M - nM) + p.y * __expf(p.x - nM);
        M = nM;
    }
    g_Ms[r] = M;
    g_Is[r] = 1.f / S;
}

// read bf16 logits, exp+scale, write fp32 probs
__global__ void __launch_bounds__(256)
k_norm(float* __restrict__ probs)
{
    int row = blockIdx.x, tid = threadIdx.x;
    float M = g_Ms[row], I = g_Is[row];
    const uint2* src = (const uint2*)(g_lbf + (size_t)row * VH);   // 2500 uint2 per row
    float4* dst = (float4*)(probs + (size_t)row * VOCAB);
#pragma unroll
    for (int r = 0; r < 10; r++) {
        int i = tid + r * 256;
        if (i < VH / 2) {
            uint2 wv = src[i];
            __nv_bfloat162 b0 = *reinterpret_cast<__nv_bfloat162*>(&wv.x);
            __nv_bfloat162 b1 = *reinterpret_cast<__nv_bfloat162*>(&wv.y);
            float4 q;
            q.x = __expf(__bfloat162float(b0.x) - M) * I;
            q.y = __expf(__bfloat162float(b0.y) - M) * I;
            q.z = __expf(__bfloat162float(b1.x) - M) * I;
            q.w = __expf(__bfloat162float(b1.y) - M) * I;
            dst[i] = q;
        }
    }
}

// ---------------- attention (reads fused qkv [row][768], writes packed split ao) --------
__global__ void __launch_bounds__(256)
k_attn(const float* __restrict__ QKV)
{
    int e = blockIdx.x;
    int tid = threadIdx.x;
    __shared__ float qs[8][DG], ks[8][DG], vs[8][DG];
    __shared__ float att[NH][8][8];

    for (int i = tid; i < 8 * DG; i += 256) {
        int s = i >> 8, c = i & 255;
        size_t base = (size_t)(e * 8 + s) * 768 + c;
        qs[s][c] = QKV[base]; ks[s][c] = QKV[base + 256]; vs[s][c] = QKV[base + 512];
    }
    __syncthreads();
    {
        int h = tid >> 6, rem = tid & 63, qi = rem >> 3, ki = rem & 7;
        float acc = 0.f;
#pragma unroll
        for (int d = 0; d < HD; d++) acc = fmaf(qs[qi][h * HD + d], ks[ki][h * HD + d], acc);
        att[h][qi][ki] = acc * 0.125f;
    }
    __syncthreads();
    if (tid < 32) {
        int h = tid >> 3, qi = tid & 7;
        float m = -1e30f;
#pragma unroll
        for (int ki = 0; ki < 8; ki++) m = fmaxf(m, att[h][qi][ki]);
        float s = 0.f, ex[8];
#pragma unroll
        for (int ki = 0; ki < 8; ki++) { ex[ki] = __expf(att[h][qi][ki] - m); s += ex[ki]; }
        float inv = 1.f / s;
#pragma unroll
        for (int ki = 0; ki < 8; ki++) att[h][qi][ki] = ex[ki] * inv;
    }
    __syncthreads();
    {
        int c = tid, h = c >> 6;
#pragma unroll
        for (int s = 0; s < 8; s++) {
            float acc = 0.f;
#pragma unroll
            for (int ki = 0; ki < 8; ki++) acc = fmaf(att[h][s][ki], vs[ki][c], acc);
            float vn = __shfl_down_sync(0xffffffffu, acc, 1);
            if ((c & 1) == 0) {
                uint32_t hi, lo;
                splitpair(acc, vn, hi, lo);
                g_sao[(size_t)(e * 8 + s) * 128 + (c >> 1)] = make_uint2(hi, lo);
            }
        }
    }
}

// ---------------- host launcher ----------------
extern "C" void kernel_launch(void* const* d_in, const int* in_sizes, int n_in,
                              void* d_out, int out_size)
{
    const int*   node_tokens = (const int*)d_in[0];
    const int*   edge_tokens = (const int*)d_in[1];
    const int*   edge_index  = (const int*)d_in[2];
    const int*   mask_rows   = (const int*)d_in[3];
    const float* emb   = (const float*)d_in[4];
    const float* W_msg = (const float*)d_in[5];
    const float* W_node= (const float*)d_in[6];
    const float* lc1_w = (const float*)d_in[7];
    const float* lc1_b = (const float*)d_in[8];
    const float* lc2_w = (const float*)d_in[9];
    const float* lc2_b = (const float*)d_in[10];
    const float* Wq  = (const float*)d_in[11];
    const float* Wk  = (const float*)d_in[12];
    const float* Wv  = (const float*)d_in[13];
    const float* Wo  = (const float*)d_in[14];
    const float* Wf1 = (const float*)d_in[15];
    const float* Wf2 = (const float*)d_in[16];
    const int* src = edge_index;
    const int* dst = edge_index + N_EDGES;

    float *p_x, *p_msg, *p_agg, *p_h, *p_zg, *p_qkv, *p_x1;
    float2* p_pstat;
    uint32_t *whi, *wlo, *plbf;
    uint2 *sse, *ssx, *sszin, *sszg, *ssao, *ssx1, *ssffn, *ssx2, *ssy;
    cudaGetSymbolAddress((void**)&p_x,   g_x);
    cudaGetSymbolAddress((void**)&p_msg, g_msg);
    cudaGetSymbolAddress((void**)&p_agg, g_agg);
    cudaGetSymbolAddress((void**)&p_h,   g_h);
    cudaGetSymbolAddress((void**)&p_zg,  g_zg);
    cudaGetSymbolAddress((void**)&p_qkv, g_qkv);
    cudaGetSymbolAddress((void**)&p_x1,  g_x1);
    cudaGetSymbolAddress((void**)&p_pstat, g_pstat);
    cudaGetSymbolAddress((void**)&whi,   g_whi);
    cudaGetSymbolAddress((void**)&wlo,   g_wlo);
    cudaGetSymbolAddress((void**)&plbf,  g_lbf);
    cudaGetSymbolAddress((void**)&sse,   g_se);
    cudaGetSymbolAddress((void**)&ssx,   g_sx);
    cudaGetSymbolAddress((void**)&sszin, g_szin);
    cudaGetSymbolAddress((void**)&sszg,  g_szg);
    cudaGetSymbolAddress((void**)&ssao,  g_sao);
    cudaGetSymbolAddress((void**)&ssx1,  g_sx1);
    cudaGetSymbolAddress((void**)&ssffn, g_sffn);
    cudaGetSymbolAddress((void**)&ssx2,  g_sx2);
    cudaGetSymbolAddress((void**)&ssy,   g_sy);

    const int SMG = (2 * 128 * 32 + 2 * 64 * 32) * 4;   // 48KB
    cudaFuncSetAttribute(tgemm<1, false, true, true, true, false>,   cudaFuncAttributeMaxDynamicSharedMemorySize, SMG);
    cudaFuncSetAttribute(tgemm<1, false, true, false, true, false>,  cudaFuncAttributeMaxDynamicSharedMemorySize, SMG);
    cudaFuncSetAttribute(tgemm<0, true, false, false, true, true>,   cudaFuncAttributeMaxDynamicSharedMemorySize, SMG);
    cudaFuncSetAttribute(tgemm<0, false, false, false, true, false>, cudaFuncAttributeMaxDynamicSharedMemorySize, SMG);
    cudaFuncSetAttribute(tgemm<0, false, true, false, true, true>,   cudaFuncAttributeMaxDynamicSharedMemorySize, SMG);
    cudaFuncSetAttribute(tgemm<2, false, false, false, false, true>, cudaFuncAttributeMaxDynamicSharedMemorySize, SMG);
    cudaFuncSetAttribute(tgemm<0, false, true, false, false, true>,  cudaFuncAttributeMaxDynamicSharedMemorySize, SMG);
    cudaFuncSetAttribute(tgemm<0, true, false, false, false, true>,  cudaFuncAttributeMaxDynamicSharedMemorySize, SMG);
    cudaFuncSetAttribute(lmg, cudaFuncAttributeMaxDynamicSharedMemorySize, SMG);

    // output layout: probs-only, or labels(16384) ++ probs
    float* out = (float*)d_out;
    const long long PROBS_N = (long long)NROWS * VOCAB;
    float* labels_out = nullptr;
    float* probs = out;
    if ((long long)out_size >= PROBS_N + NROWS) { labels_out = out; probs = out + NROWS; }

    // 1) embeds + weight presplit
    k_lab_embed_e<<<(NROWS * 16) / 256, 256>>>(edge_tokens, mask_rows, emb, labels_out);
    k_embed_x<<<(N_NODES * L_TOK * 16) / 256, 256>>>(node_tokens, emb);
    k_prep<<<(TOTAL_PAIRS + 255) / 256, 256>>>(W_msg, W_node, lc1_w, Wq, Wk, Wv, Wo, Wf1, Wf2, lc2_w, emb);

    // 2) GNN
    tgemm<1, false, true, true, true, false><<<dim3(FD / 64, N_EDGES / 128), 256, SMG>>>(
        sse, whi + OFF_WMSG, wlo + OFF_WMSG, nullptr, p_x, src, p_msg, nullptr, N_EDGES, FD, FD);
    k_zero<<<(N_NODES * FD / 4) / 256, 256>>>(p_agg, N_NODES * FD / 4);
    k_scatter<<<(N_EDGES * FD) / 256, 256>>>(p_msg, dst, p_agg);
    tgemm<1, false, true, false, true, false><<<dim3(FD / 64, N_NODES / 128), 256, SMG>>>(
        ssx, whi + OFF_WNODE, wlo + OFF_WNODE, nullptr, p_agg, nullptr, p_h, nullptr, N_NODES, FD, FD);

    // 3) eh gather + lc1
    k_zin<<<(NROWS * 16) / 256, 256>>>(p_h, src, dst);
    tgemm<0, true, false, false, true, true><<<dim3(DG / 64, NROWS / 128), 256, SMG>>>(
        sszin, whi + OFF_LC1, wlo + OFF_LC1, lc1_b, nullptr, nullptr, p_zg, sszg, NROWS, DG, D_EMB);

    // 4) transformer
    tgemm<0, false, false, false, true, false><<<dim3(768 / 64, NROWS / 128), 256, SMG>>>(
        sszg, whi + OFF_QKV, wlo + OFF_QKV, nullptr, nullptr, nullptr, p_qkv, nullptr, NROWS, 768, DG);
    k_attn<<<N_EDGES, 256>>>(p_qkv);
    tgemm<0, false, true, false, true, true><<<dim3(DG / 64, NROWS / 128), 256, SMG>>>(
        ssao, whi + OFF_WO, wlo + OFF_WO, nullptr, p_zg, nullptr, p_x1, ssx1, NROWS, DG, DG);
    tgemm<2, false, false, false, false, true><<<dim3(4 * DG / 64, NROWS / 128), 256, SMG>>>(
        ssx1, whi + OFF_WF1, wlo + OFF_WF1, nullptr, nullptr, nullptr, nullptr, ssffn, NROWS, 4 * DG, DG);
    tgemm<0, false, true, false, false, true><<<dim3(DG / 64, NROWS / 128), 256, SMG>>>(
        ssffn, whi + OFF_WF2, wlo + OFF_WF2, nullptr, p_x1, nullptr, nullptr, ssx2, NROWS, DG, 4 * DG);

    // 5) lc2 -> y (split only)
    tgemm<0, true, false, false, false, true><<<dim3(1, NROWS / 128), 256, SMG>>>(
        ssx2, whi + OFF_LC2, wlo + OFF_LC2, lc2_b, nullptr, nullptr, nullptr, ssy, NROWS, D_EMB, DG);

    // 6) lm head (bf16 logits + partial stats) -> reduce -> exp/scale to fp32 probs
    lmg<<<dim3(NVT, NROWS / 128), 256, SMG>>>(ssy, whi + OFF_EMB, plbf, p_pstat);
    k_red<<<NROWS / 256, 256>>>();
    k_norm<<<NROWS, 256>>>(probs);
}